// round 12
// baseline (speedup 1.0000x reference)
#include <cuda_runtime.h>
#include <math.h>

#define NB 32
#define NP 24564
#define NT 20
#define NC 81
#define TOT (NB * NP)
#define TOT2 (TOT / 2)

// ---- k_stream partition (grid 4800, by bid%5): 0-2 lse, 3 match, 4 rowarg ----
#define TG 4                                  // truths per match-warp
#define NTG 5                                 // truth groups (NT/TG)
#define MCHUNKS 48
#define MCHUNK 512                            // 48*512 = 24576 >= NP
#define G1_TOT 4800
#define G1_LSE 2880
#define NW_LSE (G1_LSE * 8)                   // 23040 warps
#define RA_BLOCKS 960
#define RA_STRIDE (RA_BLOCKS * 256)

#define G2 ((TOT + 255) / 256)                // 3072 blocks

// ---------------- device scratch (explicit zero-init; no allocations) ----------------
__device__ unsigned long long g_keys[NB * NT] = {};  // packed (ov_bits<<32)|~p per (b,t)
__device__ float2 g_lse2[TOT];                       // per-row {sum(exp), logit[0]}
__device__ float2 g_row[TOT];                        // per-row {bestOv, (float)bestT}
__device__ double g_accL = 0.0, g_accC = 0.0, g_accN = 0.0;
__device__ unsigned int g_ticket = 0;

// =====================================================================
// Launch 1: fused [lse stream || prior-argmax match || per-row truth-argmax]
// =====================================================================
__global__ void __launch_bounds__(256) k_stream(const float* __restrict__ conf,
                                                const float* __restrict__ priors,
                                                const float* __restrict__ targets) {
    __shared__ float4 s_box[NB * NT];
    __shared__ float  s_ta[NB * NT];

    const int bid  = blockIdx.x;
    const int tid  = threadIdx.x;
    const int lane = tid & 31;
    const int r5   = bid % 5;
    const int q5   = bid / 5;

    if (r5 == 3) {
        // ---------------- MATCH: argmax over priors per (b,t) ----------------
        const int gwarp = q5 * 8 + (tid >> 5);               // 0..7679
        const int chunk = gwarp % MCHUNKS;
        const int btg   = gwarp / MCHUNKS;                   // 0..159
        const int tg    = btg % NTG;
        const int b     = btg / NTG;

        float tx0[TG], ty0[TG], tx1[TG], ty1[TG], ta[TG];
        const float* tbase = targets + (size_t)(b * NT + tg * TG) * 5;
        #pragma unroll
        for (int j = 0; j < TG; j++) {
            tx0[j] = tbase[j * 5 + 0]; ty0[j] = tbase[j * 5 + 1];
            tx1[j] = tbase[j * 5 + 2]; ty1[j] = tbase[j * 5 + 3];
            ta[j]  = (tx1[j] - tx0[j]) * (ty1[j] - ty0[j]);
        }

        const int pend = min(NP, (chunk + 1) * MCHUNK);
        float bestOv[TG];
        int   bestP[TG];
        #pragma unroll
        for (int j = 0; j < TG; j++) { bestOv[j] = 0.0f; bestP[j] = 0; }

        #pragma unroll 4
        for (int p = chunk * MCHUNK + lane; p < pend; p += 32) {
            const float4 pr = reinterpret_cast<const float4*>(priors)[p];
            const float hz = 0.5f * pr.z, hw = 0.5f * pr.w;
            const float px0 = pr.x - hz, px1 = pr.x + hz;
            const float py0 = pr.y - hw, py1 = pr.y + hw;
            const float pa  = pr.z * pr.w;
            #pragma unroll
            for (int j = 0; j < TG; j++) {
                const float iw = fmaxf(fminf(tx1[j], px1) - fmaxf(tx0[j], px0), 0.0f);
                const float ih = fmaxf(fminf(ty1[j], py1) - fmaxf(ty0[j], py0), 0.0f);
                const float inter = iw * ih;
                const float ov = __fdividef(inter, ta[j] + pa - inter);
                if (ov > bestOv[j]) { bestOv[j] = ov; bestP[j] = p; } // smallest p in-lane
            }
        }

        #pragma unroll
        for (int j = 0; j < TG; j++) {
            unsigned long long key =
                ((unsigned long long)__float_as_uint(bestOv[j]) << 32) |
                (unsigned int)(~(unsigned int)bestP[j]);
            #pragma unroll
            for (int o = 16; o; o >>= 1) {
                unsigned long long other = __shfl_xor_sync(0xffffffffu, key, o);
                key = (other > key) ? other : key;
            }
            if (lane == 0) atomicMax(&g_keys[b * NT + tg * TG + j], key);
        }
    } else if (r5 == 4) {
        // ---------------- ROWARG: per-row argmax over 20 truths (unforced) ----------------
        for (int i = tid; i < NB * NT; i += 256) {
            const float* tg = targets + (size_t)i * 5;
            const float x0 = tg[0], y0 = tg[1], x1 = tg[2], y1 = tg[3];
            s_box[i] = make_float4(x0, y0, x1, y1);
            s_ta[i]  = (x1 - x0) * (y1 - y0);
        }
        __syncthreads();

        for (int row = q5 * 256 + tid; row < TOT; row += RA_STRIDE) {
            const int b = row / NP;
            const int p = row - b * NP;
            const int base = b * NT;

            const float4 pr = reinterpret_cast<const float4*>(priors)[p];
            const float px0 = pr.x - 0.5f * pr.z, py0 = pr.y - 0.5f * pr.w;
            const float px1 = pr.x + 0.5f * pr.z, py1 = pr.y + 0.5f * pr.w;
            const float parea = pr.z * pr.w;

            float bestOv = -1.0f;
            int bestT = 0;
            #pragma unroll
            for (int t = 0; t < NT; t++) {
                const float4 bx = s_box[base + t];
                const float iw = fmaxf(fminf(bx.z, px1) - fmaxf(bx.x, px0), 0.0f);
                const float ih = fmaxf(fminf(bx.w, py1) - fmaxf(bx.y, py0), 0.0f);
                const float inter = iw * ih;
                const float ov = __fdividef(inter, s_ta[base + t] + parea - inter);
                if (ov > bestOv) { bestOv = ov; bestT = t; }   // tie -> smallest t
            }
            g_row[row] = make_float2(bestOv, (float)bestT);
        }
    } else {
        // ---------------- LSE: unshifted logsumexp stream ----------------
        const int lb = q5 * 3 + r5;            // 0..2879
        const int hl = lane & 15;
        const int h  = lane >> 4;
        const int gw = lb * 8 + (tid >> 5);
        const int nW = NW_LSE;

        const size_t rstride = (size_t)nW * 2 * NC;
        const float* rpA = conf + (size_t)(2 * gw + h) * NC;

        int r2 = gw;
        for (; r2 + nW < TOT2; r2 += 2 * nW, rpA += 2 * rstride) {
            const float* rpB = rpA + rstride;
            const float* crA = rpA + hl;
            const float* crB = rpB + hl;

            const float a0 = __ldcs(crA),      b0 = __ldcs(crB);
            const float a1 = __ldcs(crA + 16), b1 = __ldcs(crB + 16);
            const float a2 = __ldcs(crA + 32), b2 = __ldcs(crB + 32);
            const float a3 = __ldcs(crA + 48), b3 = __ldcs(crB + 48);
            const float a4 = __ldcs(crA + 64), b4 = __ldcs(crB + 64);
            const float a5 = (hl == 0) ? __ldcs(crA + 80) : -INFINITY;
            const float b5 = (hl == 0) ? __ldcs(crB + 80) : -INFINITY;

            float eA = __expf(a0) + __expf(a1) + __expf(a2) +
                       __expf(a3) + __expf(a4) + __expf(a5);
            float eB = __expf(b0) + __expf(b1) + __expf(b2) +
                       __expf(b3) + __expf(b4) + __expf(b5);
            #pragma unroll
            for (int o = 8; o; o >>= 1) {
                eA += __shfl_xor_sync(0xffffffffu, eA, o);
                eB += __shfl_xor_sync(0xffffffffu, eB, o);
            }
            if (hl == 0) {                       // lanes 0/16: a0,b0 ARE logit[0]
                g_lse2[2 * r2 + h] = make_float2(eA, a0);
                g_lse2[2 * (r2 + nW) + h] = make_float2(eB, b0);
            }
        }
        for (; r2 < TOT2; r2 += nW, rpA += rstride) {
            const float* cr = rpA + hl;
            const float c0 = __ldcs(cr);
            const float c1 = __ldcs(cr + 16);
            const float c2 = __ldcs(cr + 32);
            const float c3 = __ldcs(cr + 48);
            const float c4 = __ldcs(cr + 64);
            const float c5 = (hl == 0) ? __ldcs(cr + 80) : -INFINITY;
            float e = __expf(c0) + __expf(c1) + __expf(c2) +
                      __expf(c3) + __expf(c4) + __expf(c5);
            #pragma unroll
            for (int o = 8; o; o >>= 1) e += __shfl_xor_sync(0xffffffffu, e, o);
            if (hl == 0) g_lse2[2 * r2 + h] = make_float2(e, c0);
        }
    }
}

// =====================================================================
// Shared per-row contribution (used by tail AND fixup for exact cancellation)
// =====================================================================
__device__ __forceinline__ float sl1f(float d) {
    float a = fabsf(d);
    return (a < 1.0f) ? 0.5f * d * d : a - 0.5f;
}

__device__ __forceinline__ void row_contrib(int row, int cls, int bestT,
                                            const float* __restrict__ loc,
                                            const float* __restrict__ conf,
                                            const float* __restrict__ priors,
                                            const float* __restrict__ targets,
                                            double& C, double& L, double& N) {
    C = 0.0; L = 0.0; N = 0.0;
    const float2 lse = g_lse2[row];
    if (cls >= 0) {
        const float lv = (cls > 0) ? __ldg(conf + (size_t)row * NC + cls) : lse.y;
        const float logpt = lv - __logf(lse.x);
        const float pt    = __expf(logpt);
        const float at    = (cls > 0) ? 0.25f : 0.75f;
        const float om    = 1.0f - pt;
        C = (double)(-at * om * om * logpt);
    }
    if (cls > 0) {
        const int b = row / NP;
        const int p = row - b * NP;
        const float4 pr = reinterpret_cast<const float4*>(priors)[p];
        const float* tb = targets + (size_t)(b * NT + bestT) * 5;
        const float x0 = tb[0], y0 = tb[1], x1 = tb[2], y1 = tb[3];
        const float4 ld = reinterpret_cast<const float4*>(loc)[row];
        const float gx  = ((x0 + x1) * 0.5f - pr.x) / (0.1f * pr.z);
        const float gy  = ((y0 + y1) * 0.5f - pr.y) / (0.1f * pr.w);
        const float gw2 = __logf((x1 - x0) / pr.z) * 5.0f;   // /0.2
        const float gh2 = __logf((y1 - y0) / pr.w) * 5.0f;
        L = (double)(sl1f(ld.x - gx) + sl1f(ld.y - gy) +
                     sl1f(ld.z - gw2) + sl1f(ld.w - gh2));
        N = 1.0;
    }
}

__device__ __forceinline__ int bp_of(int i) {
    return (int)(~(unsigned int)(g_keys[i] & 0xffffffffull));
}

// =====================================================================
// Launch 2: trivial per-row tail (unforced) + 640-entry forced fixup + finalize
// =====================================================================
__global__ void __launch_bounds__(256) k_tail(const float* __restrict__ loc,
                                              const float* __restrict__ conf,
                                              const float* __restrict__ priors,
                                              const float* __restrict__ targets,
                                              float* __restrict__ out) {
    __shared__ double sL[8], sC[8], sN[8];
    __shared__ int sLast;

    const int row = blockIdx.x * 256 + threadIdx.x;
    double myL = 0.0, myC = 0.0, myN = 0.0;

    if (row < TOT) {
        const float2 ra = g_row[row];
        const float ov = ra.x;
        const int   bt = (int)ra.y;
        int cls;
        if (ov < 0.4f) cls = 0;
        else if (ov < 0.5f) cls = -1;
        else {
            const int b = row / NP;
            cls = (int)__ldg(targets + (size_t)(b * NT + bt) * 5 + 4) + 1;
        }
        row_contrib(row, cls, bt, loc, conf, priors, targets, myC, myL, myN);
    }

    #pragma unroll
    for (int o = 16; o; o >>= 1) {
        myL += __shfl_down_sync(0xffffffffu, myL, o);
        myC += __shfl_down_sync(0xffffffffu, myC, o);
        myN += __shfl_down_sync(0xffffffffu, myN, o);
    }
    const int lane = threadIdx.x & 31, w = threadIdx.x >> 5;
    if (lane == 0) { sL[w] = myL; sC[w] = myC; sN[w] = myN; }
    if (threadIdx.x == 0) sLast = 0;
    __syncthreads();

    if (threadIdx.x == 0) {
        double tL = 0.0, tC = 0.0, tN = 0.0;
        #pragma unroll
        for (int i = 0; i < 8; i++) { tL += sL[i]; tC += sC[i]; tN += sN[i]; }
        if (tL != 0.0 || tN != 0.0) { atomicAdd(&g_accL, tL); atomicAdd(&g_accN, tN); }
        atomicAdd(&g_accC, tC);
        __threadfence();
        const unsigned my = atomicAdd(&g_ticket, 1u);
        if (my == G2 - 1) sLast = 1;
    }
    __syncthreads();

    if (sLast) {
        // ---- forced-match fixup: <=640 rows; largest t wins per duplicate p* ----
        double fL = 0.0, fC = 0.0, fN = 0.0;
        for (int i = threadIdx.x; i < NB * NT; i += 256) {
            const int b = i / NT, t = i - b * NT;
            const int pstar = bp_of(i);
            bool skip = false;
            for (int t2 = t + 1; t2 < NT; t2++)
                if (bp_of(b * NT + t2) == pstar) { skip = true; break; }
            if (!skip) {
                const int r2 = b * NP + pstar;
                // unforced contribution (mirrors main path exactly -> cancels)
                const float2 ra = g_row[r2];
                const float ov = ra.x;
                const int   bt = (int)ra.y;
                int cls_u;
                if (ov < 0.4f) cls_u = 0;
                else if (ov < 0.5f) cls_u = -1;
                else cls_u = (int)__ldg(targets + (size_t)(b * NT + bt) * 5 + 4) + 1;
                double Cu, Lu, Nu;
                row_contrib(r2, cls_u, bt, loc, conf, priors, targets, Cu, Lu, Nu);
                // forced: ov := 2.0 -> positive with truth t
                const int cls_f = (int)__ldg(targets + (size_t)(b * NT + t) * 5 + 4) + 1;
                double Cf, Lf, Nf;
                row_contrib(r2, cls_f, t, loc, conf, priors, targets, Cf, Lf, Nf);
                fC += Cf - Cu; fL += Lf - Lu; fN += Nf - Nu;
            }
        }
        #pragma unroll
        for (int o = 16; o; o >>= 1) {
            fL += __shfl_down_sync(0xffffffffu, fL, o);
            fC += __shfl_down_sync(0xffffffffu, fC, o);
            fN += __shfl_down_sync(0xffffffffu, fN, o);
        }
        if (lane == 0) { sL[w] = fL; sC[w] = fC; sN[w] = fN; }
        __syncthreads();

        if (threadIdx.x == 0) {
            double tL = 0.0, tC = 0.0, tN = 0.0;
            #pragma unroll
            for (int i = 0; i < 8; i++) { tL += sL[i]; tC += sC[i]; tN += sN[i]; }
            const double L = *(volatile double*)&g_accL + tL;
            const double C = *(volatile double*)&g_accC + tC;
            const double N = *(volatile double*)&g_accN + tN;
            out[0] = (float)(L / N);
            out[1] = (float)(C / N);
            *(volatile double*)&g_accL = 0.0;              // reset for next replay
            *(volatile double*)&g_accC = 0.0;
            *(volatile double*)&g_accN = 0.0;
            *(volatile unsigned int*)&g_ticket = 0u;
        }
        // reset g_keys for the next graph replay (fix reads are done: synced above)
        for (int i = threadIdx.x; i < NB * NT; i += 256) g_keys[i] = 0ull;
    }
}

// ---------------- launch ----------------
extern "C" void kernel_launch(void* const* d_in, const int* in_sizes, int n_in,
                              void* d_out, int out_size) {
    const float* loc     = (const float*)d_in[0];
    const float* conf    = (const float*)d_in[1];
    const float* priors  = (const float*)d_in[2];
    const float* targets = (const float*)d_in[3];
    float* out = (float*)d_out;

    k_stream<<<G1_TOT, 256>>>(conf, priors, targets);
    k_tail<<<G2, 256>>>(loc, conf, priors, targets, out);
}